// round 9
// baseline (speedup 1.0000x reference)
#include <cuda_runtime.h>
#include <cstdint>

#define DIM      64
#define TILE_M   128
#define THREADS  256

// ---- shared memory: A hi/lo tiles (SW128) + per-row norm^2 ----
#define SM_A_HI  0
#define SM_A_LO  (SM_A_HI + TILE_M * 128)     // 16 KB each
#define SM_N2    (SM_A_LO + TILE_M * 128)
#define SM_TOTAL (SM_N2 + TILE_M * 4)         // 33280 B

// fused rho B-fragments: [kk][nblock j][lane] = (bh0, bh1, bl0, bl1)
__device__ uint4 g_b[4][8][32];

static __device__ __forceinline__ uint32_t smem_u32(const void* p) {
    uint32_t a;
    asm("{ .reg .u64 t; cvta.to.shared.u64 t, %1; cvt.u32.u64 %0, t; }"
        : "=r"(a) : "l"(p));
    return a;
}

static __device__ __forceinline__ uint32_t sw128(uint32_t off) {
    return off ^ ((off >> 3) & 0x70u);
}

// pack two fp32 -> bf16x2 (a low half, b high half) + residual pair
static __device__ __forceinline__ void split_pair(float a, float b,
                                                  uint32_t& hi, uint32_t& lo) {
    uint32_t h;
    asm("cvt.rn.bf16x2.f32 %0, %1, %2;" : "=r"(h) : "f"(b), "f"(a));
    float ha = __uint_as_float(h << 16);
    float hb = __uint_as_float(h & 0xFFFF0000u);
    uint32_t l;
    float la = a - ha, lb = b - hb;
    asm("cvt.rn.bf16x2.f32 %0, %1, %2;" : "=r"(l) : "f"(lb), "f"(la));
    hi = h; lo = l;
}

static __device__ __forceinline__ void ldsm4(uint32_t* r, uint32_t addr) {
    asm volatile("ldmatrix.sync.aligned.m8n8.x4.shared.b16 {%0,%1,%2,%3}, [%4];"
                 : "=r"(r[0]), "=r"(r[1]), "=r"(r[2]), "=r"(r[3]) : "r"(addr));
}

static __device__ __forceinline__ void mma_bf16(float* d, const uint32_t* a,
                                                uint32_t b0, uint32_t b1) {
    asm volatile(
        "mma.sync.aligned.m16n8k16.row.col.f32.bf16.bf16.f32 "
        "{%0,%1,%2,%3}, {%4,%5,%6,%7}, {%8,%9}, {%0,%1,%2,%3};"
        : "+f"(d[0]), "+f"(d[1]), "+f"(d[2]), "+f"(d[3])
        : "r"(a[0]), "r"(a[1]), "r"(a[2]), "r"(a[3]), "r"(b0), "r"(b1));
}

static __device__ __forceinline__ float bf16lo(uint32_t v) {
    return __uint_as_float(v << 16);
}
static __device__ __forceinline__ float bf16hi(uint32_t v) {
    return __uint_as_float(v & 0xFFFF0000u);
}

// ---- setup: split rho into fused B-fragment table (runs once) ----
__global__ void rho_split_kernel(const float* __restrict__ rho) {
    const int t = blockIdx.x * blockDim.x + threadIdx.x;   // 0..1023
    const int lane = t & 31;
    const int j    = (t >> 5) & 7;
    const int kk   = t >> 8;
    const int n  = j * 8 + (lane >> 2);
    const int k0 = kk * 16 + (lane & 3) * 2;
    const float v0 = rho[n * DIM + k0],     v1 = rho[n * DIM + k0 + 1];
    const float v2 = rho[n * DIM + k0 + 8], v3 = rho[n * DIM + k0 + 9];
    uint32_t h0, l0, h1, l1;
    split_pair(v0, v1, h0, l0);
    split_pair(v2, v3, h1, l1);
    g_b[kk][j][lane] = make_uint4(h0, h1, l0, l1);
}

__global__ void __launch_bounds__(THREADS, 4)
qmeas_kernel(const float* __restrict__ x, float* __restrict__ out, int nrows) {
    extern __shared__ char smem[];
    const uint32_t sb = smem_u32(smem);
    float* n2s = (float*)(smem + SM_N2);

    const int tid  = threadIdx.x;
    const int lane = tid & 31;
    const int wid  = tid >> 5;              // 0..7, warp owns 16 rows

    const long blkbase = (long)blockIdx.x * TILE_M;

    // ---- load half an x row per thread (fp32), norm^2, split -> SW128 tiles
    {
        const int r  = tid >> 1;            // 0..127 local row
        const int cb = (tid & 1) * 32;      // column base
        const long grow = blkbase + r;
        float xv[32];
        float norm2 = 0.f;
        if (grow < (long)nrows) {
            const float4* xp = (const float4*)(x + (size_t)grow * DIM + cb);
            #pragma unroll
            for (int i = 0; i < 8; i++) {
                float4 v = xp[i];
                xv[4*i+0] = v.x; xv[4*i+1] = v.y; xv[4*i+2] = v.z; xv[4*i+3] = v.w;
                norm2 += v.x*v.x + v.y*v.y + v.z*v.z + v.w*v.w;
            }
        } else {
            #pragma unroll
            for (int i = 0; i < 32; i++) xv[i] = 0.f;
        }
        norm2 += __shfl_xor_sync(0xFFFFFFFFu, norm2, 1);
        if ((tid & 1) == 0) n2s[r] = norm2;

        #pragma unroll
        for (int c = 0; c < 4; c++) {
            uint32_t hi[4], lo[4];
            #pragma unroll
            for (int p = 0; p < 4; p++)
                split_pair(xv[c*8 + 2*p], xv[c*8 + 2*p + 1], hi[p], lo[p]);
            uint32_t off = sw128((uint32_t)r * 128u + (uint32_t)(cb * 2 + c * 16));
            asm volatile("st.shared.v4.b32 [%0], {%1,%2,%3,%4};"
                         :: "r"(sb + SM_A_HI + off), "r"(hi[0]), "r"(hi[1]), "r"(hi[2]), "r"(hi[3])
                         : "memory");
            asm volatile("st.shared.v4.b32 [%0], {%1,%2,%3,%4};"
                         :: "r"(sb + SM_A_LO + off), "r"(lo[0]), "r"(lo[1]), "r"(lo[2]), "r"(lo[3])
                         : "memory");
        }
    }
    __syncthreads();

    // ---- hoist ALL A-fragments (hi+lo, 4 k-steps) into registers ----
    const int mbase = wid * 16;
    const int lane7 = lane & 7;
    const int agrp  = lane >> 3;
    const uint32_t kA = (uint32_t)((agrp >> 1) * 16);
    const uint32_t arow = (uint32_t)(mbase + (agrp & 1) * 8 + lane7) * 128u;

    uint32_t ah[4][4], al[4][4];
    #pragma unroll
    for (int kk = 0; kk < 4; kk++) {
        const uint32_t off = sw128(arow + (uint32_t)(kk * 32) + kA);
        ldsm4(ah[kk], sb + SM_A_HI + off);
        ldsm4(al[kk], sb + SM_A_LO + off);
    }

    // ---- j-outer GEMM + fused dot epilogue (acc retired per j) ----
    const int r0 = lane >> 2;
    const int cq = (lane & 3) * 2;
    const int rowA = mbase + r0;
    const int rowB = rowA + 8;
    float dA = 0.f, dB = 0.f;

    #pragma unroll
    for (int j = 0; j < 8; j++) {
        float acc[4] = {0.f, 0.f, 0.f, 0.f};
        #pragma unroll
        for (int kk = 0; kk < 4; kk++) {
            const uint4 b = g_b[kk][j][lane];
            mma_bf16(acc, ah[kk], b.x, b.y);
            mma_bf16(acc, al[kk], b.x, b.y);
            mma_bf16(acc, ah[kk], b.z, b.w);
        }
        // fold this j-block into the per-row dot (x reconstructed hi+lo)
        const uint32_t cbyte = (uint32_t)(j * 8 + cq) * 2u;
        const uint32_t offA = sw128((uint32_t)rowA * 128u + cbyte);
        const uint32_t offB = sw128((uint32_t)rowB * 128u + cbyte);
        const uint32_t hA = *(const uint32_t*)(smem + SM_A_HI + offA);
        const uint32_t lA = *(const uint32_t*)(smem + SM_A_LO + offA);
        const uint32_t hB = *(const uint32_t*)(smem + SM_A_HI + offB);
        const uint32_t lB = *(const uint32_t*)(smem + SM_A_LO + offB);
        dA += (bf16lo(hA) + bf16lo(lA)) * acc[0]
            + (bf16hi(hA) + bf16hi(lA)) * acc[1];
        dB += (bf16lo(hB) + bf16lo(lB)) * acc[2]
            + (bf16hi(hB) + bf16hi(lB)) * acc[3];
    }

    // quad-lane reduce: lanes {l, l^1, l^2} cover all 64 columns
    dA += __shfl_xor_sync(0xFFFFFFFFu, dA, 1);
    dA += __shfl_xor_sync(0xFFFFFFFFu, dA, 2);
    dB += __shfl_xor_sync(0xFFFFFFFFu, dB, 1);
    dB += __shfl_xor_sync(0xFFFFFFFFu, dB, 2);

    if ((lane & 3) == 0) {
        const long gA = blkbase + rowA;
        const long gB = blkbase + rowB;
        if (gA < (long)nrows) out[gA] = n2s[rowA] * dA;
        if (gB < (long)nrows) out[gB] = n2s[rowB] * dB;
    }
}

extern "C" void kernel_launch(void* const* d_in, const int* in_sizes, int n_in,
                              void* d_out, int out_size) {
    const float* x   = (const float*)d_in[0];
    const float* rho = (const float*)d_in[1];
    float* out = (float*)d_out;
    const int nrows = out_size;

    cudaFuncSetAttribute(qmeas_kernel,
                         cudaFuncAttributeMaxDynamicSharedMemorySize, SM_TOTAL);

    rho_split_kernel<<<4, 256>>>(rho);
    const int grid = (nrows + TILE_M - 1) / TILE_M;
    qmeas_kernel<<<grid, THREADS, SM_TOTAL>>>(x, out, nrows);
}

// round 11
// speedup vs baseline: 1.0851x; 1.0851x over previous
#include <cuda_runtime.h>
#include <cstdint>

#define DIM      64
#define TILE_M   256
#define THREADS  256

// ---- shared memory: A hi/lo tiles (SW128) + per-row norm^2 ----
#define SM_A_HI  0
#define SM_A_LO  (SM_A_HI + TILE_M * 128)     // 32 KB each
#define SM_N2    (SM_A_LO + TILE_M * 128)
#define SM_TOTAL (SM_N2 + TILE_M * 4)         // 66560 B

// fused rho B-fragments: [kk][nblock j][lane] = (bh0, bh1, bl0, bl1)
__device__ uint4 g_b[4][8][32];

static __device__ __forceinline__ uint32_t smem_u32(const void* p) {
    uint32_t a;
    asm("{ .reg .u64 t; cvta.to.shared.u64 t, %1; cvt.u32.u64 %0, t; }"
        : "=r"(a) : "l"(p));
    return a;
}

static __device__ __forceinline__ uint32_t sw128(uint32_t off) {
    return off ^ ((off >> 3) & 0x70u);
}

// pack two fp32 -> bf16x2 (a low half, b high half) + residual pair
static __device__ __forceinline__ void split_pair(float a, float b,
                                                  uint32_t& hi, uint32_t& lo) {
    uint32_t h;
    asm("cvt.rn.bf16x2.f32 %0, %1, %2;" : "=r"(h) : "f"(b), "f"(a));
    float ha = __uint_as_float(h << 16);
    float hb = __uint_as_float(h & 0xFFFF0000u);
    uint32_t l;
    float la = a - ha, lb = b - hb;
    asm("cvt.rn.bf16x2.f32 %0, %1, %2;" : "=r"(l) : "f"(lb), "f"(la));
    hi = h; lo = l;
}

static __device__ __forceinline__ void ldsm4(uint32_t* r, uint32_t addr) {
    asm volatile("ldmatrix.sync.aligned.m8n8.x4.shared.b16 {%0,%1,%2,%3}, [%4];"
                 : "=r"(r[0]), "=r"(r[1]), "=r"(r[2]), "=r"(r[3]) : "r"(addr));
}

static __device__ __forceinline__ void mma_bf16(float* d, const uint32_t* a,
                                                uint32_t b0, uint32_t b1) {
    asm volatile(
        "mma.sync.aligned.m16n8k16.row.col.f32.bf16.bf16.f32 "
        "{%0,%1,%2,%3}, {%4,%5,%6,%7}, {%8,%9}, {%0,%1,%2,%3};"
        : "+f"(d[0]), "+f"(d[1]), "+f"(d[2]), "+f"(d[3])
        : "r"(a[0]), "r"(a[1]), "r"(a[2]), "r"(a[3]), "r"(b0), "r"(b1));
}

static __device__ __forceinline__ float bf16lo(uint32_t v) {
    return __uint_as_float(v << 16);
}
static __device__ __forceinline__ float bf16hi(uint32_t v) {
    return __uint_as_float(v & 0xFFFF0000u);
}

// ---- setup: split rho into fused B-fragment table (runs once) ----
__global__ void rho_split_kernel(const float* __restrict__ rho) {
    const int t = blockIdx.x * blockDim.x + threadIdx.x;   // 0..1023
    const int lane = t & 31;
    const int j    = (t >> 5) & 7;
    const int kk   = t >> 8;
    const int n  = j * 8 + (lane >> 2);
    const int k0 = kk * 16 + (lane & 3) * 2;
    const float v0 = rho[n * DIM + k0],     v1 = rho[n * DIM + k0 + 1];
    const float v2 = rho[n * DIM + k0 + 8], v3 = rho[n * DIM + k0 + 9];
    uint32_t h0, l0, h1, l1;
    split_pair(v0, v1, h0, l0);
    split_pair(v2, v3, h1, l1);
    g_b[kk][j][lane] = make_uint4(h0, h1, l0, l1);
}

__global__ void __launch_bounds__(THREADS, 2)
qmeas_kernel(const float* __restrict__ x, float* __restrict__ out, int nrows) {
    extern __shared__ char smem[];
    const uint32_t sb = smem_u32(smem);
    float* n2s = (float*)(smem + SM_N2);

    const int tid  = threadIdx.x;
    const int lane = tid & 31;
    const int wid  = tid >> 5;              // 0..7, warp owns 32 rows

    const long blkbase = (long)blockIdx.x * TILE_M;

    // ---- load x (2 halves of 128 rows), norm^2, split -> SW128 hi/lo tiles
    #pragma unroll
    for (int h = 0; h < 2; h++) {
        const int r  = h * 128 + (tid >> 1);   // local row
        const int cb = (tid & 1) * 32;         // column base
        const long grow = blkbase + r;
        float xv[32];
        float norm2 = 0.f;
        if (grow < (long)nrows) {
            const float4* xp = (const float4*)(x + (size_t)grow * DIM + cb);
            #pragma unroll
            for (int i = 0; i < 8; i++) {
                float4 v = xp[i];
                xv[4*i+0] = v.x; xv[4*i+1] = v.y; xv[4*i+2] = v.z; xv[4*i+3] = v.w;
                norm2 += v.x*v.x + v.y*v.y + v.z*v.z + v.w*v.w;
            }
        } else {
            #pragma unroll
            for (int i = 0; i < 32; i++) xv[i] = 0.f;
        }
        norm2 += __shfl_xor_sync(0xFFFFFFFFu, norm2, 1);
        if ((tid & 1) == 0) n2s[r] = norm2;

        #pragma unroll
        for (int c = 0; c < 4; c++) {
            uint32_t hi[4], lo[4];
            #pragma unroll
            for (int p = 0; p < 4; p++)
                split_pair(xv[c*8 + 2*p], xv[c*8 + 2*p + 1], hi[p], lo[p]);
            uint32_t off = sw128((uint32_t)r * 128u + (uint32_t)(cb * 2 + c * 16));
            asm volatile("st.shared.v4.b32 [%0], {%1,%2,%3,%4};"
                         :: "r"(sb + SM_A_HI + off), "r"(hi[0]), "r"(hi[1]), "r"(hi[2]), "r"(hi[3])
                         : "memory");
            asm volatile("st.shared.v4.b32 [%0], {%1,%2,%3,%4};"
                         :: "r"(sb + SM_A_LO + off), "r"(lo[0]), "r"(lo[1]), "r"(lo[2]), "r"(lo[3])
                         : "memory");
        }
    }
    __syncthreads();

    // ---- GEMM1: Y[32,64] per warp = X_tile * rho^T (3-term bf16 split) ----
    // kk-outer keeps 16 independent accumulator chains (2 m-tiles x 8 j).
    const int mbase = wid * 32;
    const int lane7 = lane & 7;
    const int agrp  = lane >> 3;
    const uint32_t kA = (uint32_t)((agrp >> 1) * 16);
    uint32_t arow[2];
    #pragma unroll
    for (int t = 0; t < 2; t++)
        arow[t] = (uint32_t)(mbase + t*16 + (agrp & 1)*8 + lane7) * 128u;

    float acc[2][8][4];
    #pragma unroll
    for (int t = 0; t < 2; t++)
        #pragma unroll
        for (int j = 0; j < 8; j++)
            #pragma unroll
            for (int q = 0; q < 4; q++) acc[t][j][q] = 0.f;

    #pragma unroll
    for (int kk = 0; kk < 4; kk++) {
        uint32_t ah[2][4], al[2][4];
        #pragma unroll
        for (int t = 0; t < 2; t++) {
            const uint32_t off = sw128(arow[t] + (uint32_t)(kk * 32) + kA);
            ldsm4(ah[t], sb + SM_A_HI + off);
            ldsm4(al[t], sb + SM_A_LO + off);
        }
        #pragma unroll
        for (int j = 0; j < 8; j++) {
            const uint4 b = g_b[kk][j][lane];
            mma_bf16(acc[0][j], ah[0], b.x, b.y);
            mma_bf16(acc[1][j], ah[1], b.x, b.y);
            mma_bf16(acc[0][j], al[0], b.x, b.y);
            mma_bf16(acc[1][j], al[1], b.x, b.y);
            mma_bf16(acc[0][j], ah[0], b.z, b.w);
            mma_bf16(acc[1][j], ah[1], b.z, b.w);
        }
    }

    // ---- epilogue: dot(x_row, y_row) in fp32 via FFMA; x = hi+lo from smem
    const int r0 = lane >> 2;
    const int cq = (lane & 3) * 2;
    #pragma unroll
    for (int t = 0; t < 2; t++) {
        const int rowA = mbase + 16*t + r0;
        const int rowB = rowA + 8;
        float dA = 0.f, dB = 0.f;
        #pragma unroll
        for (int j = 0; j < 8; j++) {
            const uint32_t cbyte = (uint32_t)(j * 8 + cq) * 2u;
            const uint32_t offA = sw128((uint32_t)rowA * 128u + cbyte);
            const uint32_t offB = sw128((uint32_t)rowB * 128u + cbyte);
            const uint32_t hA = *(const uint32_t*)(smem + SM_A_HI + offA);
            const uint32_t lA = *(const uint32_t*)(smem + SM_A_LO + offA);
            const uint32_t hB = *(const uint32_t*)(smem + SM_A_HI + offB);
            const uint32_t lB = *(const uint32_t*)(smem + SM_A_LO + offB);
            dA += (bf16lo(hA) + bf16lo(lA)) * acc[t][j][0]
                + (bf16hi(hA) + bf16hi(lA)) * acc[t][j][1];
            dB += (bf16lo(hB) + bf16lo(lB)) * acc[t][j][2]
                + (bf16hi(hB) + bf16hi(lB)) * acc[t][j][3];
        }
        // quad-lane reduce: lanes {l, l^1, l^2} cover all 64 columns
        dA += __shfl_xor_sync(0xFFFFFFFFu, dA, 1);
        dA += __shfl_xor_sync(0xFFFFFFFFu, dA, 2);
        dB += __shfl_xor_sync(0xFFFFFFFFu, dB, 1);
        dB += __shfl_xor_sync(0xFFFFFFFFu, dB, 2);

        if ((lane & 3) == 0) {
            const long gA = blkbase + rowA;
            const long gB = blkbase + rowB;
            if (gA < (long)nrows) out[gA] = n2s[rowA] * dA;
            if (gB < (long)nrows) out[gB] = n2s[rowB] * dB;
        }
    }
}

extern "C" void kernel_launch(void* const* d_in, const int* in_sizes, int n_in,
                              void* d_out, int out_size) {
    const float* x   = (const float*)d_in[0];
    const float* rho = (const float*)d_in[1];
    float* out = (float*)d_out;
    const int nrows = out_size;

    cudaFuncSetAttribute(qmeas_kernel,
                         cudaFuncAttributeMaxDynamicSharedMemorySize, SM_TOTAL);

    rho_split_kernel<<<4, 256>>>(rho);
    const int grid = (nrows + TILE_M - 1) / TILE_M;
    qmeas_kernel<<<grid, THREADS, SM_TOTAL>>>(x, out, nrows);
}

// round 12
// speedup vs baseline: 1.2173x; 1.1219x over previous
#include <cuda_runtime.h>
#include <cuda_fp16.h>
#include <cstdint>

#define DIM      64
#define TILE_M   256
#define THREADS  256

// ---- shared memory: A hi/lo tiles (SW128) + per-row norm^2 ----
#define SM_A_HI  0
#define SM_A_LO  (SM_A_HI + TILE_M * 128)     // 32 KB each
#define SM_N2    (SM_A_LO + TILE_M * 128)
#define SM_TOTAL (SM_N2 + TILE_M * 4)         // 66560 B

// rho B-fragments (fp16 hi only): [kk][nblock j][lane] = (b0, b1)
__device__ uint2 g_b[4][8][32];

static __device__ __forceinline__ uint32_t smem_u32(const void* p) {
    uint32_t a;
    asm("{ .reg .u64 t; cvta.to.shared.u64 t, %1; cvt.u32.u64 %0, t; }"
        : "=r"(a) : "l"(p));
    return a;
}

static __device__ __forceinline__ uint32_t sw128(uint32_t off) {
    return off ^ ((off >> 3) & 0x70u);
}

// pack two fp32 -> f16x2 (a low half, b high half) + exact residual pair
static __device__ __forceinline__ void split_pair_f16(float a, float b,
                                                      uint32_t& hi, uint32_t& lo) {
    uint32_t h;
    asm("cvt.rn.f16x2.f32 %0, %1, %2;" : "=r"(h) : "f"(b), "f"(a));
    const __half2 hh = *reinterpret_cast<const __half2*>(&h);
    const float ha = __low2float(hh);
    const float hb = __high2float(hh);
    uint32_t l;
    const float la = a - ha, lb = b - hb;
    asm("cvt.rn.f16x2.f32 %0, %1, %2;" : "=r"(l) : "f"(lb), "f"(la));
    hi = h; lo = l;
}

static __device__ __forceinline__ float f16lo(uint32_t v) {
    return __low2float(*reinterpret_cast<const __half2*>(&v));
}
static __device__ __forceinline__ float f16hi(uint32_t v) {
    return __high2float(*reinterpret_cast<const __half2*>(&v));
}

static __device__ __forceinline__ void ldsm4(uint32_t* r, uint32_t addr) {
    asm volatile("ldmatrix.sync.aligned.m8n8.x4.shared.b16 {%0,%1,%2,%3}, [%4];"
                 : "=r"(r[0]), "=r"(r[1]), "=r"(r[2]), "=r"(r[3]) : "r"(addr));
}

static __device__ __forceinline__ void mma_f16(float* d, const uint32_t* a,
                                               uint32_t b0, uint32_t b1) {
    asm volatile(
        "mma.sync.aligned.m16n8k16.row.col.f32.f16.f16.f32 "
        "{%0,%1,%2,%3}, {%4,%5,%6,%7}, {%8,%9}, {%0,%1,%2,%3};"
        : "+f"(d[0]), "+f"(d[1]), "+f"(d[2]), "+f"(d[3])
        : "r"(a[0]), "r"(a[1]), "r"(a[2]), "r"(a[3]), "r"(b0), "r"(b1));
}

// ---- setup: rho -> fp16 B-fragment table (runs once) ----
__global__ void rho_split_kernel(const float* __restrict__ rho) {
    const int t = blockIdx.x * blockDim.x + threadIdx.x;   // 0..1023
    const int lane = t & 31;
    const int j    = (t >> 5) & 7;
    const int kk   = t >> 8;
    const int n  = j * 8 + (lane >> 2);
    const int k0 = kk * 16 + (lane & 3) * 2;
    const float v0 = rho[n * DIM + k0],     v1 = rho[n * DIM + k0 + 1];
    const float v2 = rho[n * DIM + k0 + 8], v3 = rho[n * DIM + k0 + 9];
    uint32_t h0, h1;
    asm("cvt.rn.f16x2.f32 %0, %1, %2;" : "=r"(h0) : "f"(v1), "f"(v0));
    asm("cvt.rn.f16x2.f32 %0, %1, %2;" : "=r"(h1) : "f"(v3), "f"(v2));
    g_b[kk][j][lane] = make_uint2(h0, h1);
}

__global__ void __launch_bounds__(THREADS, 2)
qmeas_kernel(const float* __restrict__ x, float* __restrict__ out, int nrows) {
    extern __shared__ char smem[];
    const uint32_t sb = smem_u32(smem);
    float* n2s = (float*)(smem + SM_N2);

    const int tid  = threadIdx.x;
    const int lane = tid & 31;
    const int wid  = tid >> 5;              // 0..7, warp owns 32 rows

    const long blkbase = (long)blockIdx.x * TILE_M;

    // ---- load x (2 halves of 128 rows), norm^2, split -> SW128 hi/lo tiles
    #pragma unroll
    for (int h = 0; h < 2; h++) {
        const int r  = h * 128 + (tid >> 1);   // local row
        const int cb = (tid & 1) * 32;         // column base
        const long grow = blkbase + r;
        float xv[32];
        float norm2 = 0.f;
        if (grow < (long)nrows) {
            const float4* xp = (const float4*)(x + (size_t)grow * DIM + cb);
            #pragma unroll
            for (int i = 0; i < 8; i++) {
                float4 v = xp[i];
                xv[4*i+0] = v.x; xv[4*i+1] = v.y; xv[4*i+2] = v.z; xv[4*i+3] = v.w;
                norm2 += v.x*v.x + v.y*v.y + v.z*v.z + v.w*v.w;
            }
        } else {
            #pragma unroll
            for (int i = 0; i < 32; i++) xv[i] = 0.f;
        }
        norm2 += __shfl_xor_sync(0xFFFFFFFFu, norm2, 1);
        if ((tid & 1) == 0) n2s[r] = norm2;

        #pragma unroll
        for (int c = 0; c < 4; c++) {
            uint32_t hi[4], lo[4];
            #pragma unroll
            for (int p = 0; p < 4; p++)
                split_pair_f16(xv[c*8 + 2*p], xv[c*8 + 2*p + 1], hi[p], lo[p]);
            uint32_t off = sw128((uint32_t)r * 128u + (uint32_t)(cb * 2 + c * 16));
            asm volatile("st.shared.v4.b32 [%0], {%1,%2,%3,%4};"
                         :: "r"(sb + SM_A_HI + off), "r"(hi[0]), "r"(hi[1]), "r"(hi[2]), "r"(hi[3])
                         : "memory");
            asm volatile("st.shared.v4.b32 [%0], {%1,%2,%3,%4};"
                         :: "r"(sb + SM_A_LO + off), "r"(lo[0]), "r"(lo[1]), "r"(lo[2]), "r"(lo[3])
                         : "memory");
        }
    }
    __syncthreads();

    // ---- GEMM1: Y[32,64] per warp = X_tile * rho^T (fp16 2-term split) ----
    // kk-outer keeps 16 independent accumulator chains (2 m-tiles x 8 j).
    const int mbase = wid * 32;
    const int lane7 = lane & 7;
    const int agrp  = lane >> 3;
    const uint32_t kA = (uint32_t)((agrp >> 1) * 16);
    uint32_t arow[2];
    #pragma unroll
    for (int t = 0; t < 2; t++)
        arow[t] = (uint32_t)(mbase + t*16 + (agrp & 1)*8 + lane7) * 128u;

    float acc[2][8][4];
    #pragma unroll
    for (int t = 0; t < 2; t++)
        #pragma unroll
        for (int j = 0; j < 8; j++)
            #pragma unroll
            for (int q = 0; q < 4; q++) acc[t][j][q] = 0.f;

    #pragma unroll
    for (int kk = 0; kk < 4; kk++) {
        uint32_t ah[2][4], al[2][4];
        #pragma unroll
        for (int t = 0; t < 2; t++) {
            const uint32_t off = sw128(arow[t] + (uint32_t)(kk * 32) + kA);
            ldsm4(ah[t], sb + SM_A_HI + off);
            ldsm4(al[t], sb + SM_A_LO + off);
        }
        #pragma unroll
        for (int j = 0; j < 8; j++) {
            const uint2 b = g_b[kk][j][lane];
            mma_f16(acc[0][j], ah[0], b.x, b.y);
            mma_f16(acc[1][j], ah[1], b.x, b.y);
            mma_f16(acc[0][j], al[0], b.x, b.y);
            mma_f16(acc[1][j], al[1], b.x, b.y);
        }
    }

    // ---- epilogue: dot(x_row, y_row) in fp32 via FFMA; x = hi+lo from smem
    const int r0 = lane >> 2;
    const int cq = (lane & 3) * 2;
    #pragma unroll
    for (int t = 0; t < 2; t++) {
        const int rowA = mbase + 16*t + r0;
        const int rowB = rowA + 8;
        float dA = 0.f, dB = 0.f;
        #pragma unroll
        for (int j = 0; j < 8; j++) {
            const uint32_t cbyte = (uint32_t)(j * 8 + cq) * 2u;
            const uint32_t offA = sw128((uint32_t)rowA * 128u + cbyte);
            const uint32_t offB = sw128((uint32_t)rowB * 128u + cbyte);
            const uint32_t hA = *(const uint32_t*)(smem + SM_A_HI + offA);
            const uint32_t lA = *(const uint32_t*)(smem + SM_A_LO + offA);
            const uint32_t hB = *(const uint32_t*)(smem + SM_A_HI + offB);
            const uint32_t lB = *(const uint32_t*)(smem + SM_A_LO + offB);
            dA += (f16lo(hA) + f16lo(lA)) * acc[t][j][0]
                + (f16hi(hA) + f16hi(lA)) * acc[t][j][1];
            dB += (f16lo(hB) + f16lo(lB)) * acc[t][j][2]
                + (f16hi(hB) + f16hi(lB)) * acc[t][j][3];
        }
        // quad-lane reduce: lanes {l, l^1, l^2} cover all 64 columns
        dA += __shfl_xor_sync(0xFFFFFFFFu, dA, 1);
        dA += __shfl_xor_sync(0xFFFFFFFFu, dA, 2);
        dB += __shfl_xor_sync(0xFFFFFFFFu, dB, 1);
        dB += __shfl_xor_sync(0xFFFFFFFFu, dB, 2);

        if ((lane & 3) == 0) {
            const long gA = blkbase + rowA;
            const long gB = blkbase + rowB;
            if (gA < (long)nrows) out[gA] = n2s[rowA] * dA;
            if (gB < (long)nrows) out[gB] = n2s[rowB] * dB;
        }
    }
}

extern "C" void kernel_launch(void* const* d_in, const int* in_sizes, int n_in,
                              void* d_out, int out_size) {
    const float* x   = (const float*)d_in[0];
    const float* rho = (const float*)d_in[1];
    float* out = (float*)d_out;
    const int nrows = out_size;

    cudaFuncSetAttribute(qmeas_kernel,
                         cudaFuncAttributeMaxDynamicSharedMemorySize, SM_TOTAL);

    rho_split_kernel<<<4, 256>>>(rho);
    const int grid = (nrows + TILE_M - 1) / TILE_M;
    qmeas_kernel<<<grid, THREADS, SM_TOTAL>>>(x, out, nrows);
}

// round 14
// speedup vs baseline: 1.3558x; 1.1138x over previous
#include <cuda_runtime.h>
#include <cuda_fp16.h>
#include <cstdint>

#define DIM      64
#define TILE_M   256
#define THREADS  256

// ---- shared memory: A hi/lo tiles (SW128) + rho table + per-row norm^2 ----
#define SM_A_HI  0
#define SM_A_LO  (SM_A_HI + TILE_M * 128)     // 32 KB each
#define SM_B     (SM_A_LO + TILE_M * 128)     // 8 KB rho fragment table
#define SM_N2    (SM_B + 4 * 8 * 32 * 8)
#define SM_TOTAL (SM_N2 + TILE_M * 4)         // 74752 B

// rho B-fragments (fp16): [kk][nblock j][lane] = (b0, b1)
__device__ uint2 g_b[4][8][32];

static __device__ __forceinline__ uint32_t smem_u32(const void* p) {
    uint32_t a;
    asm("{ .reg .u64 t; cvta.to.shared.u64 t, %1; cvt.u32.u64 %0, t; }"
        : "=r"(a) : "l"(p));
    return a;
}

static __device__ __forceinline__ uint32_t sw128(uint32_t off) {
    return off ^ ((off >> 3) & 0x70u);
}

// pack two fp32 -> f16x2 (a low half, b high half) + exact residual pair
static __device__ __forceinline__ void split_pair_f16(float a, float b,
                                                      uint32_t& hi, uint32_t& lo) {
    uint32_t h;
    asm("cvt.rn.f16x2.f32 %0, %1, %2;" : "=r"(h) : "f"(b), "f"(a));
    const __half2 hh = *reinterpret_cast<const __half2*>(&h);
    const float ha = __low2float(hh);
    const float hb = __high2float(hh);
    uint32_t l;
    const float la = a - ha, lb = b - hb;
    asm("cvt.rn.f16x2.f32 %0, %1, %2;" : "=r"(l) : "f"(lb), "f"(la));
    hi = h; lo = l;
}

static __device__ __forceinline__ float f16lo(uint32_t v) {
    return __low2float(*reinterpret_cast<const __half2*>(&v));
}
static __device__ __forceinline__ float f16hi(uint32_t v) {
    return __high2float(*reinterpret_cast<const __half2*>(&v));
}

static __device__ __forceinline__ void ldsm4(uint32_t* r, uint32_t addr) {
    asm volatile("ldmatrix.sync.aligned.m8n8.x4.shared.b16 {%0,%1,%2,%3}, [%4];"
                 : "=r"(r[0]), "=r"(r[1]), "=r"(r[2]), "=r"(r[3]) : "r"(addr));
}

static __device__ __forceinline__ void mma_f16(float* d, const uint32_t* a,
                                               uint32_t b0, uint32_t b1) {
    asm volatile(
        "mma.sync.aligned.m16n8k16.row.col.f32.f16.f16.f32 "
        "{%0,%1,%2,%3}, {%4,%5,%6,%7}, {%8,%9}, {%0,%1,%2,%3};"
        : "+f"(d[0]), "+f"(d[1]), "+f"(d[2]), "+f"(d[3])
        : "r"(a[0]), "r"(a[1]), "r"(a[2]), "r"(a[3]), "r"(b0), "r"(b1));
}

// ---- setup: rho -> fp16 B-fragment table (runs once) ----
__global__ void rho_split_kernel(const float* __restrict__ rho) {
    const int t = blockIdx.x * blockDim.x + threadIdx.x;   // 0..1023
    const int lane = t & 31;
    const int j    = (t >> 5) & 7;
    const int kk   = t >> 8;
    const int n  = j * 8 + (lane >> 2);
    const int k0 = kk * 16 + (lane & 3) * 2;
    const float v0 = rho[n * DIM + k0],     v1 = rho[n * DIM + k0 + 1];
    const float v2 = rho[n * DIM + k0 + 8], v3 = rho[n * DIM + k0 + 9];
    uint32_t h0, h1;
    asm("cvt.rn.f16x2.f32 %0, %1, %2;" : "=r"(h0) : "f"(v1), "f"(v0));
    asm("cvt.rn.f16x2.f32 %0, %1, %2;" : "=r"(h1) : "f"(v3), "f"(v2));
    g_b[kk][j][lane] = make_uint2(h0, h1);
}

__global__ void __launch_bounds__(THREADS, 2)
qmeas_kernel(const float* __restrict__ x, float* __restrict__ out, int nrows) {
    extern __shared__ char smem[];
    const uint32_t sb = smem_u32(smem);
    float* n2s = (float*)(smem + SM_N2);
    uint2* btab = (uint2*)(smem + SM_B);

    const int tid  = threadIdx.x;
    const int lane = tid & 31;
    const int wid  = tid >> 5;              // 0..7, warp owns 32 rows

    const long blkbase = (long)blockIdx.x * TILE_M;

    // ---- preload rho fragment table into smem (8 KB, 4 uint2 per thread) ----
    {
        const uint2* gsrc = &g_b[0][0][0];
        #pragma unroll
        for (int i = 0; i < 4; i++)
            btab[tid + i * 256] = gsrc[tid + i * 256];
    }

    // ---- load x (2 halves of 128 rows), norm^2, split -> SW128 hi/lo tiles
    #pragma unroll
    for (int h = 0; h < 2; h++) {
        const int r  = h * 128 + (tid >> 1);   // local row
        const int cb = (tid & 1) * 32;         // column base
        const long grow = blkbase + r;
        float xv[32];
        float norm2 = 0.f;
        if (grow < (long)nrows) {
            const float4* xp = (const float4*)(x + (size_t)grow * DIM + cb);
            #pragma unroll
            for (int i = 0; i < 8; i++) {
                float4 v = xp[i];
                xv[4*i+0] = v.x; xv[4*i+1] = v.y; xv[4*i+2] = v.z; xv[4*i+3] = v.w;
                norm2 += v.x*v.x + v.y*v.y + v.z*v.z + v.w*v.w;
            }
        } else {
            #pragma unroll
            for (int i = 0; i < 32; i++) xv[i] = 0.f;
        }
        norm2 += __shfl_xor_sync(0xFFFFFFFFu, norm2, 1);
        if ((tid & 1) == 0) n2s[r] = norm2;

        #pragma unroll
        for (int c = 0; c < 4; c++) {
            uint32_t hi[4], lo[4];
            #pragma unroll
            for (int p = 0; p < 4; p++)
                split_pair_f16(xv[c*8 + 2*p], xv[c*8 + 2*p + 1], hi[p], lo[p]);
            uint32_t off = sw128((uint32_t)r * 128u + (uint32_t)(cb * 2 + c * 16));
            asm volatile("st.shared.v4.b32 [%0], {%1,%2,%3,%4};"
                         :: "r"(sb + SM_A_HI + off), "r"(hi[0]), "r"(hi[1]), "r"(hi[2]), "r"(hi[3])
                         : "memory");
            asm volatile("st.shared.v4.b32 [%0], {%1,%2,%3,%4};"
                         :: "r"(sb + SM_A_LO + off), "r"(lo[0]), "r"(lo[1]), "r"(lo[2]), "r"(lo[3])
                         : "memory");
        }
    }
    __syncthreads();

    // ---- GEMM1: Y[32,64] per warp = X_tile * rho^T (fp16 2-term split) ----
    // kk-outer keeps 16 independent accumulator chains (2 m-tiles x 8 j).
    const int mbase = wid * 32;
    const int lane7 = lane & 7;
    const int agrp  = lane >> 3;
    const uint32_t kA = (uint32_t)((agrp >> 1) * 16);
    uint32_t arow[2];
    #pragma unroll
    for (int t = 0; t < 2; t++)
        arow[t] = (uint32_t)(mbase + t*16 + (agrp & 1)*8 + lane7) * 128u;

    float acc[2][8][4];
    #pragma unroll
    for (int t = 0; t < 2; t++)
        #pragma unroll
        for (int j = 0; j < 8; j++)
            #pragma unroll
            for (int q = 0; q < 4; q++) acc[t][j][q] = 0.f;

    #pragma unroll
    for (int kk = 0; kk < 4; kk++) {
        uint32_t ah[2][4], al[2][4];
        #pragma unroll
        for (int t = 0; t < 2; t++) {
            const uint32_t off = sw128(arow[t] + (uint32_t)(kk * 32) + kA);
            ldsm4(ah[t], sb + SM_A_HI + off);
            ldsm4(al[t], sb + SM_A_LO + off);
        }
        #pragma unroll
        for (int j = 0; j < 8; j++) {
            const uint2 b = btab[(kk * 8 + j) * 32 + lane];
            mma_f16(acc[0][j], ah[0], b.x, b.y);
            mma_f16(acc[1][j], ah[1], b.x, b.y);
            mma_f16(acc[0][j], al[0], b.x, b.y);
            mma_f16(acc[1][j], al[1], b.x, b.y);
        }
    }

    // ---- epilogue: dot(x_row, y_row) in fp32 via FFMA; x ~= x_hi from smem
    // (dropped x_lo term ~2^-12 relative, inside tolerance)
    const int r0 = lane >> 2;
    const int cq = (lane & 3) * 2;
    #pragma unroll
    for (int t = 0; t < 2; t++) {
        const int rowA = mbase + 16*t + r0;
        const int rowB = rowA + 8;
        float dA = 0.f, dB = 0.f;
        #pragma unroll
        for (int j = 0; j < 8; j++) {
            const uint32_t cbyte = (uint32_t)(j * 8 + cq) * 2u;
            const uint32_t offA = sw128((uint32_t)rowA * 128u + cbyte);
            const uint32_t offB = sw128((uint32_t)rowB * 128u + cbyte);
            const uint32_t hA = *(const uint32_t*)(smem + SM_A_HI + offA);
            const uint32_t hB = *(const uint32_t*)(smem + SM_A_HI + offB);
            dA += f16lo(hA) * acc[t][j][0] + f16hi(hA) * acc[t][j][1];
            dB += f16lo(hB) * acc[t][j][2] + f16hi(hB) * acc[t][j][3];
        }
        // quad-lane reduce: lanes {l, l^1, l^2} cover all 64 columns
        dA += __shfl_xor_sync(0xFFFFFFFFu, dA, 1);
        dA += __shfl_xor_sync(0xFFFFFFFFu, dA, 2);
        dB += __shfl_xor_sync(0xFFFFFFFFu, dB, 1);
        dB += __shfl_xor_sync(0xFFFFFFFFu, dB, 2);

        if ((lane & 3) == 0) {
            const long gA = blkbase + rowA;
            const long gB = blkbase + rowB;
            if (gA < (long)nrows) out[gA] = n2s[rowA] * dA;
            if (gB < (long)nrows) out[gB] = n2s[rowB] * dB;
        }
    }
}

extern "C" void kernel_launch(void* const* d_in, const int* in_sizes, int n_in,
                              void* d_out, int out_size) {
    const float* x   = (const float*)d_in[0];
    const float* rho = (const float*)d_in[1];
    float* out = (float*)d_out;
    const int nrows = out_size;

    cudaFuncSetAttribute(qmeas_kernel,
                         cudaFuncAttributeMaxDynamicSharedMemorySize, SM_TOTAL);

    rho_split_kernel<<<4, 256>>>(rho);
    const int grid = (nrows + TILE_M - 1) / TILE_M;
    qmeas_kernel<<<grid, THREADS, SM_TOTAL>>>(x, out, nrows);
}

// round 15
// speedup vs baseline: 1.3695x; 1.0101x over previous
#include <cuda_runtime.h>
#include <cuda_fp16.h>
#include <cstdint>

#define DIM      64
#define TILE_M   256
#define THREADS  256

// ---- shared memory: A hi tile (SW128) + rho table + per-row norm^2 ----
#define SM_A_HI  0
#define SM_B     (SM_A_HI + TILE_M * 128)     // 32 KB tile, then 8 KB table
#define SM_N2    (SM_B + 4 * 8 * 32 * 8)
#define SM_TOTAL (SM_N2 + TILE_M * 4)         // 41984 B

// rho B-fragments (fp16): [kk][nblock j][lane] = (b0, b1)
__device__ uint2 g_b[4][8][32];

static __device__ __forceinline__ uint32_t smem_u32(const void* p) {
    uint32_t a;
    asm("{ .reg .u64 t; cvta.to.shared.u64 t, %1; cvt.u32.u64 %0, t; }"
        : "=r"(a) : "l"(p));
    return a;
}

static __device__ __forceinline__ uint32_t sw128(uint32_t off) {
    return off ^ ((off >> 3) & 0x70u);
}

static __device__ __forceinline__ float f16lo(uint32_t v) {
    return __low2float(*reinterpret_cast<const __half2*>(&v));
}
static __device__ __forceinline__ float f16hi(uint32_t v) {
    return __high2float(*reinterpret_cast<const __half2*>(&v));
}

static __device__ __forceinline__ void ldsm4(uint32_t* r, uint32_t addr) {
    asm volatile("ldmatrix.sync.aligned.m8n8.x4.shared.b16 {%0,%1,%2,%3}, [%4];"
                 : "=r"(r[0]), "=r"(r[1]), "=r"(r[2]), "=r"(r[3]) : "r"(addr));
}

static __device__ __forceinline__ void mma_f16(float* d, const uint32_t* a,
                                               uint32_t b0, uint32_t b1) {
    asm volatile(
        "mma.sync.aligned.m16n8k16.row.col.f32.f16.f16.f32 "
        "{%0,%1,%2,%3}, {%4,%5,%6,%7}, {%8,%9}, {%0,%1,%2,%3};"
        : "+f"(d[0]), "+f"(d[1]), "+f"(d[2]), "+f"(d[3])
        : "r"(a[0]), "r"(a[1]), "r"(a[2]), "r"(a[3]), "r"(b0), "r"(b1));
}

// ---- setup: rho -> fp16 B-fragment table (runs once) ----
__global__ void rho_split_kernel(const float* __restrict__ rho) {
    const int t = blockIdx.x * blockDim.x + threadIdx.x;   // 0..1023
    const int lane = t & 31;
    const int j    = (t >> 5) & 7;
    const int kk   = t >> 8;
    const int n  = j * 8 + (lane >> 2);
    const int k0 = kk * 16 + (lane & 3) * 2;
    const float v0 = rho[n * DIM + k0],     v1 = rho[n * DIM + k0 + 1];
    const float v2 = rho[n * DIM + k0 + 8], v3 = rho[n * DIM + k0 + 9];
    uint32_t h0, h1;
    asm("cvt.rn.f16x2.f32 %0, %1, %2;" : "=r"(h0) : "f"(v1), "f"(v0));
    asm("cvt.rn.f16x2.f32 %0, %1, %2;" : "=r"(h1) : "f"(v3), "f"(v2));
    g_b[kk][j][lane] = make_uint2(h0, h1);
}

__global__ void __launch_bounds__(THREADS, 2)
qmeas_kernel(const float* __restrict__ x, float* __restrict__ out, int nrows) {
    extern __shared__ char smem[];
    const uint32_t sb = smem_u32(smem);
    float* n2s = (float*)(smem + SM_N2);
    uint2* btab = (uint2*)(smem + SM_B);

    const int tid  = threadIdx.x;
    const int lane = tid & 31;
    const int wid  = tid >> 5;              // 0..7, warp owns 32 rows

    const long blkbase = (long)blockIdx.x * TILE_M;

    // ---- preload rho fragment table into smem (8 KB, 4 uint2 per thread) ----
    {
        const uint2* gsrc = &g_b[0][0][0];
        #pragma unroll
        for (int i = 0; i < 4; i++)
            btab[tid + i * 256] = gsrc[tid + i * 256];
    }

    // ---- load x (2 halves of 128 rows), norm^2, f16 convert -> SW128 tile
    #pragma unroll
    for (int h = 0; h < 2; h++) {
        const int r  = h * 128 + (tid >> 1);   // local row
        const int cb = (tid & 1) * 32;         // column base
        const long grow = blkbase + r;
        float xv[32];
        float norm2 = 0.f;
        if (grow < (long)nrows) {
            const float4* xp = (const float4*)(x + (size_t)grow * DIM + cb);
            #pragma unroll
            for (int i = 0; i < 8; i++) {
                float4 v = xp[i];
                xv[4*i+0] = v.x; xv[4*i+1] = v.y; xv[4*i+2] = v.z; xv[4*i+3] = v.w;
                norm2 += v.x*v.x + v.y*v.y + v.z*v.z + v.w*v.w;
            }
        } else {
            #pragma unroll
            for (int i = 0; i < 32; i++) xv[i] = 0.f;
        }
        norm2 += __shfl_xor_sync(0xFFFFFFFFu, norm2, 1);
        if ((tid & 1) == 0) n2s[r] = norm2;

        #pragma unroll
        for (int c = 0; c < 4; c++) {
            uint32_t hi[4];
            #pragma unroll
            for (int p = 0; p < 4; p++)
                asm("cvt.rn.f16x2.f32 %0, %1, %2;"
                    : "=r"(hi[p]) : "f"(xv[c*8 + 2*p + 1]), "f"(xv[c*8 + 2*p]));
            uint32_t off = sw128((uint32_t)r * 128u + (uint32_t)(cb * 2 + c * 16));
            asm volatile("st.shared.v4.b32 [%0], {%1,%2,%3,%4};"
                         :: "r"(sb + SM_A_HI + off), "r"(hi[0]), "r"(hi[1]), "r"(hi[2]), "r"(hi[3])
                         : "memory");
        }
    }
    __syncthreads();

    // ---- GEMM1: Y[32,64] per warp = X_tile * rho^T (single-term fp16) ----
    // kk-outer keeps 16 independent accumulator chains (2 m-tiles x 8 j).
    const int mbase = wid * 32;
    const int lane7 = lane & 7;
    const int agrp  = lane >> 3;
    const uint32_t kA = (uint32_t)((agrp >> 1) * 16);
    uint32_t arow[2];
    #pragma unroll
    for (int t = 0; t < 2; t++)
        arow[t] = (uint32_t)(mbase + t*16 + (agrp & 1)*8 + lane7) * 128u;

    float acc[2][8][4];
    #pragma unroll
    for (int t = 0; t < 2; t++)
        #pragma unroll
        for (int j = 0; j < 8; j++)
            #pragma unroll
            for (int q = 0; q < 4; q++) acc[t][j][q] = 0.f;

    #pragma unroll
    for (int kk = 0; kk < 4; kk++) {
        uint32_t ah[2][4];
        #pragma unroll
        for (int t = 0; t < 2; t++) {
            const uint32_t off = sw128(arow[t] + (uint32_t)(kk * 32) + kA);
            ldsm4(ah[t], sb + SM_A_HI + off);
        }
        #pragma unroll
        for (int j = 0; j < 8; j++) {
            const uint2 b = btab[(kk * 8 + j) * 32 + lane];
            mma_f16(acc[0][j], ah[0], b.x, b.y);
            mma_f16(acc[1][j], ah[1], b.x, b.y);
        }
    }

    // ---- epilogue: dot(x_hi_row, y_row) in fp32 via FFMA ----
    const int r0 = lane >> 2;
    const int cq = (lane & 3) * 2;
    #pragma unroll
    for (int t = 0; t < 2; t++) {
        const int rowA = mbase + 16*t + r0;
        const int rowB = rowA + 8;
        float dA = 0.f, dB = 0.f;
        #pragma unroll
        for (int j = 0; j < 8; j++) {
            const uint32_t cbyte = (uint32_t)(j * 8 + cq) * 2u;
            const uint32_t offA = sw128((uint32_t)rowA * 128u + cbyte);
            const uint32_t offB = sw128((uint32_t)rowB * 128u + cbyte);
            const uint32_t hA = *(const uint32_t*)(smem + SM_A_HI + offA);
            const uint32_t hB = *(const uint32_t*)(smem + SM_A_HI + offB);
            dA += f16lo(hA) * acc[t][j][0] + f16hi(hA) * acc[t][j][1];
            dB += f16lo(hB) * acc[t][j][2] + f16hi(hB) * acc[t][j][3];
        }
        // quad-lane reduce: lanes {l, l^1, l^2} cover all 64 columns
        dA += __shfl_xor_sync(0xFFFFFFFFu, dA, 1);
        dA += __shfl_xor_sync(0xFFFFFFFFu, dA, 2);
        dB += __shfl_xor_sync(0xFFFFFFFFu, dB, 1);
        dB += __shfl_xor_sync(0xFFFFFFFFu, dB, 2);

        if ((lane & 3) == 0) {
            const long gA = blkbase + rowA;
            const long gB = blkbase + rowB;
            if (gA < (long)nrows) out[gA] = n2s[rowA] * dA;
            if (gB < (long)nrows) out[gB] = n2s[rowB] * dB;
        }
    }
}

extern "C" void kernel_launch(void* const* d_in, const int* in_sizes, int n_in,
                              void* d_out, int out_size) {
    const float* x   = (const float*)d_in[0];
    const float* rho = (const float*)d_in[1];
    float* out = (float*)d_out;
    const int nrows = out_size;

    cudaFuncSetAttribute(qmeas_kernel,
                         cudaFuncAttributeMaxDynamicSharedMemorySize, SM_TOTAL);

    rho_split_kernel<<<4, 256>>>(rho);
    const int grid = (nrows + TILE_M - 1) / TILE_M;
    qmeas_kernel<<<grid, THREADS, SM_TOTAL>>>(x, out, nrows);
}

// round 16
// speedup vs baseline: 1.4063x; 1.0268x over previous
#include <cuda_runtime.h>
#include <cuda_fp16.h>
#include <cstdint>

#define DIM      64
#define TILE_M   128
#define THREADS  256

// ---- shared memory: A hi tile (SW128) + rho table + per-row norm^2 ----
#define SM_A_HI  0
#define SM_B     (SM_A_HI + TILE_M * 128)     // 16 KB tile, then 8 KB table
#define SM_N2    (SM_B + 4 * 8 * 32 * 8)
#define SM_TOTAL (SM_N2 + TILE_M * 4)         // 25088 B

// rho B-fragments (fp16): [kk][nblock j][lane] = (b0, b1)
__device__ uint2 g_b[4][8][32];

static __device__ __forceinline__ uint32_t smem_u32(const void* p) {
    uint32_t a;
    asm("{ .reg .u64 t; cvta.to.shared.u64 t, %1; cvt.u32.u64 %0, t; }"
        : "=r"(a) : "l"(p));
    return a;
}

static __device__ __forceinline__ uint32_t sw128(uint32_t off) {
    return off ^ ((off >> 3) & 0x70u);
}

static __device__ __forceinline__ float f16lo(uint32_t v) {
    return __low2float(*reinterpret_cast<const __half2*>(&v));
}
static __device__ __forceinline__ float f16hi(uint32_t v) {
    return __high2float(*reinterpret_cast<const __half2*>(&v));
}

static __device__ __forceinline__ void ldsm4(uint32_t* r, uint32_t addr) {
    asm volatile("ldmatrix.sync.aligned.m8n8.x4.shared.b16 {%0,%1,%2,%3}, [%4];"
                 : "=r"(r[0]), "=r"(r[1]), "=r"(r[2]), "=r"(r[3]) : "r"(addr));
}

static __device__ __forceinline__ void mma_f16(float* d, const uint32_t* a,
                                               uint32_t b0, uint32_t b1) {
    asm volatile(
        "mma.sync.aligned.m16n8k16.row.col.f32.f16.f16.f32 "
        "{%0,%1,%2,%3}, {%4,%5,%6,%7}, {%8,%9}, {%0,%1,%2,%3};"
        : "+f"(d[0]), "+f"(d[1]), "+f"(d[2]), "+f"(d[3])
        : "r"(a[0]), "r"(a[1]), "r"(a[2]), "r"(a[3]), "r"(b0), "r"(b1));
}

// ---- setup: rho -> fp16 B-fragment table (runs once) ----
__global__ void rho_split_kernel(const float* __restrict__ rho) {
    const int t = blockIdx.x * blockDim.x + threadIdx.x;   // 0..1023
    const int lane = t & 31;
    const int j    = (t >> 5) & 7;
    const int kk   = t >> 8;
    const int n  = j * 8 + (lane >> 2);
    const int k0 = kk * 16 + (lane & 3) * 2;
    const float v0 = rho[n * DIM + k0],     v1 = rho[n * DIM + k0 + 1];
    const float v2 = rho[n * DIM + k0 + 8], v3 = rho[n * DIM + k0 + 9];
    uint32_t h0, h1;
    asm("cvt.rn.f16x2.f32 %0, %1, %2;" : "=r"(h0) : "f"(v1), "f"(v0));
    asm("cvt.rn.f16x2.f32 %0, %1, %2;" : "=r"(h1) : "f"(v3), "f"(v2));
    g_b[kk][j][lane] = make_uint2(h0, h1);
}

__global__ void __launch_bounds__(THREADS, 4)
qmeas_kernel(const float* __restrict__ x, float* __restrict__ out, int nrows) {
    extern __shared__ char smem[];
    const uint32_t sb = smem_u32(smem);
    float* n2s = (float*)(smem + SM_N2);
    uint2* btab = (uint2*)(smem + SM_B);

    const int tid  = threadIdx.x;
    const int lane = tid & 31;
    const int wid  = tid >> 5;              // 0..7, warp owns 16 rows

    const long blkbase = (long)blockIdx.x * TILE_M;

    // ---- preload rho fragment table into smem (8 KB, 4 uint2 per thread) ----
    {
        const uint2* gsrc = &g_b[0][0][0];
        #pragma unroll
        for (int i = 0; i < 4; i++)
            btab[tid + i * 256] = gsrc[tid + i * 256];
    }

    // ---- load half an x row per thread, norm^2, f16 convert -> SW128 tile
    {
        const int r  = tid >> 1;               // local row 0..127
        const int cb = (tid & 1) * 32;         // column base
        const long grow = blkbase + r;
        float xv[32];
        float norm2 = 0.f;
        if (grow < (long)nrows) {
            const float4* xp = (const float4*)(x + (size_t)grow * DIM + cb);
            #pragma unroll
            for (int i = 0; i < 8; i++) {
                float4 v = xp[i];
                xv[4*i+0] = v.x; xv[4*i+1] = v.y; xv[4*i+2] = v.z; xv[4*i+3] = v.w;
                norm2 += v.x*v.x + v.y*v.y + v.z*v.z + v.w*v.w;
            }
        } else {
            #pragma unroll
            for (int i = 0; i < 32; i++) xv[i] = 0.f;
        }
        norm2 += __shfl_xor_sync(0xFFFFFFFFu, norm2, 1);
        if ((tid & 1) == 0) n2s[r] = norm2;

        #pragma unroll
        for (int c = 0; c < 4; c++) {
            uint32_t hi[4];
            #pragma unroll
            for (int p = 0; p < 4; p++)
                asm("cvt.rn.f16x2.f32 %0, %1, %2;"
                    : "=r"(hi[p]) : "f"(xv[c*8 + 2*p + 1]), "f"(xv[c*8 + 2*p]));
            uint32_t off = sw128((uint32_t)r * 128u + (uint32_t)(cb * 2 + c * 16));
            asm volatile("st.shared.v4.b32 [%0], {%1,%2,%3,%4};"
                         :: "r"(sb + SM_A_HI + off), "r"(hi[0]), "r"(hi[1]), "r"(hi[2]), "r"(hi[3])
                         : "memory");
        }
    }
    __syncthreads();

    // ---- GEMM1: Y[16,64] per warp = X_tile * rho^T (single-term fp16) ----
    // kk-outer: per kk, 8 independent j-chains on one A fragment.
    const int mbase = wid * 16;
    const int lane7 = lane & 7;
    const int agrp  = lane >> 3;
    const uint32_t kA = (uint32_t)((agrp >> 1) * 16);
    const uint32_t arow = (uint32_t)(mbase + (agrp & 1) * 8 + lane7) * 128u;

    float acc[8][4];
    #pragma unroll
    for (int j = 0; j < 8; j++)
        #pragma unroll
        for (int q = 0; q < 4; q++) acc[j][q] = 0.f;

    #pragma unroll
    for (int kk = 0; kk < 4; kk++) {
        uint32_t ah[4];
        ldsm4(ah, sb + SM_A_HI + sw128(arow + (uint32_t)(kk * 32) + kA));
        #pragma unroll
        for (int j = 0; j < 8; j++) {
            const uint2 b = btab[(kk * 8 + j) * 32 + lane];
            mma_f16(acc[j], ah, b.x, b.y);
        }
    }

    // ---- epilogue: dot(x_hi_row, y_row) in fp32 via FFMA ----
    const int r0 = lane >> 2;
    const int cq = (lane & 3) * 2;
    const int rowA = mbase + r0;
    const int rowB = rowA + 8;
    float dA = 0.f, dB = 0.f;
    #pragma unroll
    for (int j = 0; j < 8; j++) {
        const uint32_t cbyte = (uint32_t)(j * 8 + cq) * 2u;
        const uint32_t offA = sw128((uint32_t)rowA * 128u + cbyte);
        const uint32_t offB = sw128((uint32_t)rowB * 128u + cbyte);
        const uint32_t hA = *(const uint32_t*)(smem + SM_A_HI + offA);
        const uint32_t hB = *(const uint32_t*)(smem + SM_A_HI + offB);
        dA += f16lo(hA) * acc[j][0] + f16hi(hA) * acc[j][1];
        dB += f16lo(hB) * acc[j][2] + f16hi(hB) * acc[j][3];
    }
    // quad-lane reduce: lanes {l, l^1, l^2} cover all 64 columns
    dA += __shfl_xor_sync(0xFFFFFFFFu, dA, 1);
    dA += __shfl_xor_sync(0xFFFFFFFFu, dA, 2);
    dB += __shfl_xor_sync(0xFFFFFFFFu, dB, 1);
    dB += __shfl_xor_sync(0xFFFFFFFFu, dB, 2);

    if ((lane & 3) == 0) {
        const long gA = blkbase + rowA;
        const long gB = blkbase + rowB;
        if (gA < (long)nrows) out[gA] = n2s[rowA] * dA;
        if (gB < (long)nrows) out[gB] = n2s[rowB] * dB;
    }
}

extern "C" void kernel_launch(void* const* d_in, const int* in_sizes, int n_in,
                              void* d_out, int out_size) {
    const float* x   = (const float*)d_in[0];
    const float* rho = (const float*)d_in[1];
    float* out = (float*)d_out;
    const int nrows = out_size;

    cudaFuncSetAttribute(qmeas_kernel,
                         cudaFuncAttributeMaxDynamicSharedMemorySize, SM_TOTAL);

    rho_split_kernel<<<4, 256>>>(rho);
    const int grid = (nrows + TILE_M - 1) / TILE_M;
    qmeas_kernel<<<grid, THREADS, SM_TOTAL>>>(x, out, nrows);
}

// round 17
// speedup vs baseline: 1.4221x; 1.0113x over previous
#include <cuda_runtime.h>
#include <cuda_fp16.h>
#include <cstdint>

#define DIM      64
#define TILE_M   128
#define THREADS  256

// ---- shared memory: A hi tile (SW128) + rho table + per-row norm^2 ----
#define SM_A_HI  0
#define SM_B     (SM_A_HI + TILE_M * 128)     // 16 KB tile, then 8 KB table
#define SM_N2    (SM_B + 2 * 8 * 32 * 16)
#define SM_TOTAL (SM_N2 + TILE_M * 4)         // 25088 B

// rho B-fragments (fp16), k-step pairs packed:
// [kkp][nblock j][lane] = (kk=2kkp: b0,b1 | kk=2kkp+1: b0,b1)
__device__ uint4 g_b[2][8][32];

static __device__ __forceinline__ uint32_t smem_u32(const void* p) {
    uint32_t a;
    asm("{ .reg .u64 t; cvta.to.shared.u64 t, %1; cvt.u32.u64 %0, t; }"
        : "=r"(a) : "l"(p));
    return a;
}

static __device__ __forceinline__ uint32_t sw128(uint32_t off) {
    return off ^ ((off >> 3) & 0x70u);
}

static __device__ __forceinline__ float f16lo(uint32_t v) {
    return __low2float(*reinterpret_cast<const __half2*>(&v));
}
static __device__ __forceinline__ float f16hi(uint32_t v) {
    return __high2float(*reinterpret_cast<const __half2*>(&v));
}

static __device__ __forceinline__ void ldsm4(uint32_t* r, uint32_t addr) {
    asm volatile("ldmatrix.sync.aligned.m8n8.x4.shared.b16 {%0,%1,%2,%3}, [%4];"
                 : "=r"(r[0]), "=r"(r[1]), "=r"(r[2]), "=r"(r[3]) : "r"(addr));
}

static __device__ __forceinline__ void mma_f16(float* d, const uint32_t* a,
                                               uint32_t b0, uint32_t b1) {
    asm volatile(
        "mma.sync.aligned.m16n8k16.row.col.f32.f16.f16.f32 "
        "{%0,%1,%2,%3}, {%4,%5,%6,%7}, {%8,%9}, {%0,%1,%2,%3};"
        : "+f"(d[0]), "+f"(d[1]), "+f"(d[2]), "+f"(d[3])
        : "r"(a[0]), "r"(a[1]), "r"(a[2]), "r"(a[3]), "r"(b0), "r"(b1));
}

// ---- setup: rho -> fp16 B-fragment table, k-pairs packed (runs once) ----
__global__ void rho_split_kernel(const float* __restrict__ rho) {
    const int t = blockIdx.x * blockDim.x + threadIdx.x;   // 0..511
    const int lane = t & 31;
    const int j    = (t >> 5) & 7;
    const int kkp  = t >> 8;                                // 0..1
    const int n = j * 8 + (lane >> 2);
    uint32_t h[4];
    #pragma unroll
    for (int s = 0; s < 2; s++) {                           // kk = 2*kkp + s
        const int k0 = (2 * kkp + s) * 16 + (lane & 3) * 2;
        const float v0 = rho[n * DIM + k0],     v1 = rho[n * DIM + k0 + 1];
        const float v2 = rho[n * DIM + k0 + 8], v3 = rho[n * DIM + k0 + 9];
        asm("cvt.rn.f16x2.f32 %0, %1, %2;" : "=r"(h[2*s  ]) : "f"(v1), "f"(v0));
        asm("cvt.rn.f16x2.f32 %0, %1, %2;" : "=r"(h[2*s+1]) : "f"(v3), "f"(v2));
    }
    g_b[kkp][j][lane] = make_uint4(h[0], h[1], h[2], h[3]);
}

__global__ void __launch_bounds__(THREADS, 4)
qmeas_kernel(const float* __restrict__ x, float* __restrict__ out, int nrows) {
    extern __shared__ char smem[];
    const uint32_t sb = smem_u32(smem);
    float* n2s = (float*)(smem + SM_N2);
    uint4* btab = (uint4*)(smem + SM_B);

    const int tid  = threadIdx.x;
    const int lane = tid & 31;
    const int wid  = tid >> 5;              // 0..7, warp owns 16 rows

    const long blkbase = (long)blockIdx.x * TILE_M;

    // ---- preload rho fragment table into smem (8 KB, 2 uint4 per thread) ----
    {
        const uint4* gsrc = &g_b[0][0][0];
        btab[tid]       = gsrc[tid];
        btab[tid + 256] = gsrc[tid + 256];
    }

    // ---- load half an x row per thread, norm^2, f16 convert -> SW128 tile
    {
        const int r  = tid >> 1;               // local row 0..127
        const int cb = (tid & 1) * 32;         // column base
        const long grow = blkbase + r;
        float xv[32];
        float norm2 = 0.f;
        if (grow < (long)nrows) {
            const float4* xp = (const float4*)(x + (size_t)grow * DIM + cb);
            #pragma unroll
            for (int i = 0; i < 8; i++) {
                float4 v = xp[i];
                xv[4*i+0] = v.x; xv[4*i+1] = v.y; xv[4*i+2] = v.z; xv[4*i+3] = v.w;
                norm2 += v.x*v.x + v.y*v.y + v.z*v.z + v.w*v.w;
            }
        } else {
            #pragma unroll
            for (int i = 0; i < 32; i++) xv[i] = 0.f;
        }
        norm2 += __shfl_xor_sync(0xFFFFFFFFu, norm2, 1);
        if ((tid & 1) == 0) n2s[r] = norm2;

        #pragma unroll
        for (int c = 0; c < 4; c++) {
            uint32_t hi[4];
            #pragma unroll
            for (int p = 0; p < 4; p++)
                asm("cvt.rn.f16x2.f32 %0, %1, %2;"
                    : "=r"(hi[p]) : "f"(xv[c*8 + 2*p + 1]), "f"(xv[c*8 + 2*p]));
            uint32_t off = sw128((uint32_t)r * 128u + (uint32_t)(cb * 2 + c * 16));
            asm volatile("st.shared.v4.b32 [%0], {%1,%2,%3,%4};"
                         :: "r"(sb + SM_A_HI + off), "r"(hi[0]), "r"(hi[1]), "r"(hi[2]), "r"(hi[3])
                         : "memory");
        }
    }
    __syncthreads();

    // ---- GEMM1: Y[16,64] per warp = X_tile * rho^T (single-term fp16) ----
    // kkp-outer (k-step pairs): per kkp, 2 ldsm + 8 x (LDS.128 + 2 MMAs).
    const int mbase = wid * 16;
    const int lane7 = lane & 7;
    const int agrp  = lane >> 3;
    const uint32_t kA = (uint32_t)((agrp >> 1) * 16);
    const uint32_t arow = (uint32_t)(mbase + (agrp & 1) * 8 + lane7) * 128u;

    float acc[8][4];
    #pragma unroll
    for (int j = 0; j < 8; j++)
        #pragma unroll
        for (int q = 0; q < 4; q++) acc[j][q] = 0.f;

    #pragma unroll
    for (int kkp = 0; kkp < 2; kkp++) {
        uint32_t ah0[4], ah1[4];
        ldsm4(ah0, sb + SM_A_HI + sw128(arow + (uint32_t)(kkp * 64)      + kA));
        ldsm4(ah1, sb + SM_A_HI + sw128(arow + (uint32_t)(kkp * 64 + 32) + kA));
        #pragma unroll
        for (int j = 0; j < 8; j++) {
            const uint4 b = btab[(kkp * 8 + j) * 32 + lane];
            mma_f16(acc[j], ah0, b.x, b.y);
            mma_f16(acc[j], ah1, b.z, b.w);
        }
    }

    // ---- epilogue: dot(x_hi_row, y_row) in fp32 via FFMA ----
    const int r0 = lane >> 2;
    const int cq = (lane & 3) * 2;
    const int rowA = mbase + r0;
    const int rowB = rowA + 8;
    float dA = 0.f, dB = 0.f;
    #pragma unroll
    for (int j = 0; j < 8; j++) {
        const uint32_t cbyte = (uint32_t)(j * 8 + cq) * 2u;
        const uint32_t offA = sw128((uint32_t)rowA * 128u + cbyte);
        const uint32_t offB = sw128((uint32_t)rowB * 128u + cbyte);
        const uint32_t hA = *(const uint32_t*)(smem + SM_A_HI + offA);
        const uint32_t hB = *(const uint32_t*)(smem + SM_A_HI + offB);
        dA += f16lo(hA) * acc[j][0] + f16hi(hA) * acc[j][1];
        dB += f16lo(hB) * acc[j][2] + f16hi(hB) * acc[j][3];
    }
    // quad-lane reduce: lanes {l, l^1, l^2} cover all 64 columns
    dA += __shfl_xor_sync(0xFFFFFFFFu, dA, 1);
    dA += __shfl_xor_sync(0xFFFFFFFFu, dA, 2);
    dB += __shfl_xor_sync(0xFFFFFFFFu, dB, 1);
    dB += __shfl_xor_sync(0xFFFFFFFFu, dB, 2);

    if ((lane & 3) == 0) {
        const long gA = blkbase + rowA;
        const long gB = blkbase + rowB;
        if (gA < (long)nrows) out[gA] = n2s[rowA] * dA;
        if (gB < (long)nrows) out[gB] = n2s[rowB] * dB;
    }
}

extern "C" void kernel_launch(void* const* d_in, const int* in_sizes, int n_in,
                              void* d_out, int out_size) {
    const float* x   = (const float*)d_in[0];
    const float* rho = (const float*)d_in[1];
    float* out = (float*)d_out;
    const int nrows = out_size;

    cudaFuncSetAttribute(qmeas_kernel,
                         cudaFuncAttributeMaxDynamicSharedMemorySize, SM_TOTAL);

    rho_split_kernel<<<2, 256>>>(rho);
    const int grid = (nrows + TILE_M - 1) / TILE_M;
    qmeas_kernel<<<grid, THREADS, SM_TOTAL>>>(x, out, nrows);
}